// round 10
// baseline (speedup 1.0000x reference)
#include <cuda_runtime.h>
#include <stdint.h>

#define NUM_USERS 100000
#define NUM_ITEMS 50000
#define NE_MAX    1000000
#define EMB       64

// ---------------- device scratch (no allocs allowed) -------------------------
__device__ int   g_deg_u[NUM_USERS];
__device__ int   g_deg_i[NUM_ITEMS];
__device__ int   g_off_u[NUM_USERS + 1];
__device__ int   g_off_i[NUM_ITEMS + 1];
__device__ int   g_cur_u[NUM_USERS];
__device__ int   g_cur_i[NUM_ITEMS];
__device__ float g_inv_u[NUM_USERS];
__device__ float g_inv_i[NUM_ITEMS];
__device__ int   g_csr_u[NE_MAX];   // dst items grouped by src user
__device__ int   g_csr_i[NE_MAX];   // src users grouped by dst item
__device__ float g_tmp_u[(size_t)NUM_USERS * EMB];  // round-1 user output
__device__ float g_tmp_i[(size_t)NUM_ITEMS * EMB];  // round-1 item output

// ---------------- CSR build ---------------------------------------------------

__global__ void k_zero_deg() {
    int idx = blockIdx.x * blockDim.x + threadIdx.x;
    if (idx < NUM_USERS) g_deg_u[idx] = 0;
    if (idx < NUM_ITEMS) g_deg_i[idx] = 0;
}

__global__ void k_degree(const int* __restrict__ src,
                         const int* __restrict__ dst, int ne) {
    int e = blockIdx.x * blockDim.x + threadIdx.x;
    if (e < ne) {
        atomicAdd(&g_deg_u[__ldg(src + e)], 1);
        atomicAdd(&g_deg_i[__ldg(dst + e)], 1);
    }
}

// One block per array (block 0: users, block 1: items). 1024-thread chunked
// exclusive scan; also fills cursor copies and inv_deg.
__global__ void k_scan() {
    const int  which = blockIdx.x;
    const int  n     = which ? NUM_ITEMS : NUM_USERS;
    const int* deg   = which ? g_deg_i  : g_deg_u;
    int*       off   = which ? g_off_i  : g_off_u;
    int*       cur   = which ? g_cur_i  : g_cur_u;
    float*     inv   = which ? g_inv_i  : g_inv_u;

    __shared__ int ssum[1024];
    int t = threadIdx.x;
    int chunk = (n + 1023) / 1024;
    int lo = t * chunk;
    int hi = lo + chunk; if (hi > n) hi = n; if (lo > n) lo = n;

    int s = 0;
    for (int k = lo; k < hi; k++) s += deg[k];
    ssum[t] = s;
    __syncthreads();

    // Hillis-Steele inclusive scan over the 1024 partials
    for (int d = 1; d < 1024; d <<= 1) {
        int v = (t >= d) ? ssum[t - d] : 0;
        __syncthreads();
        ssum[t] += v;
        __syncthreads();
    }

    int run = (t > 0) ? ssum[t - 1] : 0;   // exclusive prefix of my chunk
    for (int k = lo; k < hi; k++) {
        int d = deg[k];
        off[k] = run;
        cur[k] = run;
        inv[k] = (d > 0) ? (1.0f / (float)d) : 0.0f;
        run += d;
    }
    if (hi == n && lo < hi) off[n] = run;
    if (n == 0 && t == 0)   off[0] = 0;
}

__global__ void k_fill(const int* __restrict__ src,
                       const int* __restrict__ dst, int ne) {
    int e = blockIdx.x * blockDim.x + threadIdx.x;
    if (e < ne) {
        int su = __ldg(src + e);
        int di = __ldg(dst + e);
        int pu = atomicAdd(&g_cur_u[su], 1);
        g_csr_u[pu] = di;
        int pi = atomicAdd(&g_cur_i[di], 1);
        g_csr_i[pi] = su;
    }
}

// ---------------- fused gather-aggregate + combine ----------------------------
// 16 lanes per destination node (one float4 chunk each). Per 16-edge group:
// each lane loads one edge index (coalesced), then shfl-broadcasts within the
// 16-lane group so all 16 gathers of a row issue back-to-back (MLP=16).
// out[node] = (sum over edges of feat_src[idx]) * inv_deg + self[node] * sw.
__global__ void k_agg(const float* __restrict__ feat_src,
                      const float* __restrict__ self,
                      const float* __restrict__ sw,
                      const int*  __restrict__ off,
                      const int*  __restrict__ csr,
                      const float* __restrict__ invdeg,
                      float* __restrict__ out, int nnodes) {
    int tid  = blockIdx.x * blockDim.x + threadIdx.x;
    int node = tid >> 4;
    int c    = tid & 15;
    int lane = threadIdx.x & 31;
    unsigned hmask = (lane < 16) ? 0x0000ffffu : 0xffff0000u;

    bool valid = node < nnodes;
    int nd = valid ? node : 0;
    int beg = __ldg(off + nd);
    int end = valid ? __ldg(off + nd + 1) : beg;

    float4 acc = make_float4(0.f, 0.f, 0.f, 0.f);

    for (int base = beg; base < end; base += 16) {
        int e   = base + c;
        int idx = (e < end) ? __ldg(csr + e) : -1;
        #pragma unroll
        for (int j = 0; j < 16; j++) {
            int s = __shfl_sync(hmask, idx, j, 16);
            if (s >= 0) {
                float4 v = __ldg((const float4*)(feat_src + (size_t)s * EMB + (size_t)c * 4));
                acc.x += v.x; acc.y += v.y; acc.z += v.z; acc.w += v.w;
            }
        }
    }

    if (valid) {
        float inv = __ldg(invdeg + node);
        float w   = __ldg(sw + node);
        size_t o  = (size_t)node * EMB + (size_t)c * 4;
        float4 se = __ldg((const float4*)(self + o));
        float4 r;
        r.x = fmaf(acc.x, inv, se.x * w);
        r.y = fmaf(acc.y, inv, se.y * w);
        r.z = fmaf(acc.z, inv, se.z * w);
        r.w = fmaf(acc.w, inv, se.w * w);
        *(float4*)(out + o) = r;
    }
}

// ---------------- launch ------------------------------------------------------
extern "C" void kernel_launch(void* const* d_in, const int* in_sizes, int n_in,
                              void* d_out, int out_size) {
    const float* user_emb = (const float*)d_in[0];
    const float* item_emb = (const float*)d_in[1];
    const float* u_sw     = (const float*)d_in[2];
    const float* i_sw     = (const float*)d_in[3];
    const int*   e_src    = (const int*)d_in[4];
    const int*   e_dst    = (const int*)d_in[5];
    const int    ne       = in_sizes[4];

    float* out_u = (float*)d_out;
    float* out_i = (float*)d_out + (size_t)NUM_USERS * EMB;

    float *tmp_u, *tmp_i, *inv_u, *inv_i;
    int *off_u, *off_i, *csr_u, *csr_i;
    cudaGetSymbolAddress((void**)&tmp_u, g_tmp_u);
    cudaGetSymbolAddress((void**)&tmp_i, g_tmp_i);
    cudaGetSymbolAddress((void**)&inv_u, g_inv_u);
    cudaGetSymbolAddress((void**)&inv_i, g_inv_i);
    cudaGetSymbolAddress((void**)&off_u, g_off_u);
    cudaGetSymbolAddress((void**)&off_i, g_off_i);
    cudaGetSymbolAddress((void**)&csr_u, g_csr_u);
    cudaGetSymbolAddress((void**)&csr_i, g_csr_i);

    const int TPB = 256;

    // ---- CSR build (every replay; deterministic work) ----
    k_zero_deg<<<(NUM_USERS + TPB - 1) / TPB, TPB>>>();
    k_degree<<<(ne + TPB - 1) / TPB, TPB>>>(e_src, e_dst, ne);
    k_scan<<<2, 1024>>>();
    k_fill<<<(ne + TPB - 1) / TPB, TPB>>>(e_src, e_dst, ne);

    int blk_i = (NUM_ITEMS * 16 + TPB - 1) / TPB;
    int blk_u = (NUM_USERS * 16 + TPB - 1) / TPB;

    // ---- round 1: inputs -> tmp ----
    k_agg<<<blk_i, TPB>>>(user_emb, item_emb, i_sw, off_i, csr_i, inv_i, tmp_i, NUM_ITEMS);
    k_agg<<<blk_u, TPB>>>(item_emb, user_emb, u_sw, off_u, csr_u, inv_u, tmp_u, NUM_USERS);

    // ---- round 2: tmp -> d_out ----
    k_agg<<<blk_i, TPB>>>(tmp_u, tmp_i, i_sw, off_i, csr_i, inv_i, out_i, NUM_ITEMS);
    k_agg<<<blk_u, TPB>>>(tmp_i, tmp_u, u_sw, off_u, csr_u, inv_u, out_u, NUM_USERS);
}